// round 13
// baseline (speedup 1.0000x reference)
#include <cuda_runtime.h>
#include <cuda_bf16.h>

// Fixed shape: B=2,000,000 rows x F=21 cols, 7 classes (targets[:,2] in
// {100..700}), range penalty on targets[:,1] vs (0, 1000).
constexpr int NF    = 21;
constexpr int BTOT  = 2000000;
constexpr int GELEM = 32 * NF;            // 672 floats per 32-row group
constexpr int NVEC  = GELEM / 4;          // 168 float4 per group
constexpr int NGRP  = BTOT / 32;          // 62500 groups

constexpr int BDIM  = 256;
constexpr int WPB   = BDIM / 32;          // 8 warps/block
constexpr int NB    = 592;                // 148 SMs * 4 CTAs
constexpr int TOTW  = NB * WPB;           // 4736 warps grid-wide
constexpr int NTHR  = NB * BDIM;          // 151552 threads grid-wide

// Balanced split: every warp does exactly ITERS groups; the remainder is
// processed vector-parallel by all threads (run FIRST: overlaps its dependent
// meta-load chains with DRAM ramp-up, and leaves the perfectly uniform main
// loop as the final phase -> minimal end-of-kernel spread).
constexpr int ITERS     = NGRP / TOTW;              // 13
constexpr int MAIN_GRP  = ITERS * TOTW;             // 61568 groups
constexpr int TAIL_GRP  = NGRP - MAIN_GRP;          // 932 groups
constexpr int NTV       = TAIL_GRP * NVEC;          // 156576 tail float4s
constexpr unsigned TAIL_ROWS = TAIL_GRP * 32;       // 29824
constexpr unsigned TAIL_ROW0 = MAIN_GRP * 32;       // 1970176
constexpr long long TAIL_E0  = (long long)MAIN_GRP * GELEM;

__device__ double       g_pa[NB];
__device__ double       g_pp[NB];
__device__ unsigned int g_ctr = 0;        // re-armed by the finishing block

__device__ __forceinline__ int i4_at(int4 t, unsigned j) {
    switch (j) { case 0u: return t.x; case 1u: return t.y; case 2u: return t.z; default: return t.w; }
}

// One float4/int4 pair in the main loop: 4 consecutive elements span at most
// 2 rows. Split sums at the row boundary; 2 shfls apply row weights.
__device__ __forceinline__ void proc_vec(
    float4 xv, int4 tv, unsigned e0, float wl, float& acc)
{
    const unsigned r0  = (e0 * 6243u) >> 17;           // e0/21, exact here
    const unsigned rem = e0 - r0 * 21u;                // 0..20

    const float d0 = xv.x - (float)tv.x;
    const float d1 = xv.y - (float)tv.y;
    const float d2 = xv.z - (float)tv.z;
    const float d3 = xv.w - (float)tv.w;

    float s0 = 0.0f, s1 = 0.0f;
    if (rem + 0u < 21u) s0 = fmaf(d0, d0, s0); else s1 = fmaf(d0, d0, s1);
    if (rem + 1u < 21u) s0 = fmaf(d1, d1, s0); else s1 = fmaf(d1, d1, s1);
    if (rem + 2u < 21u) s0 = fmaf(d2, d2, s0); else s1 = fmaf(d2, d2, s1);
    if (rem + 3u < 21u) s0 = fmaf(d3, d3, s0); else s1 = fmaf(d3, d3, s1);

    const float w0 = __shfl_sync(0xFFFFFFFFu, wl, (int)(r0 & 31u));
    const float w1 = __shfl_sync(0xFFFFFFFFu, wl, (int)((r0 + 1u) & 31u));
    acc = fmaf(w0, s0, acc);
    acc = fmaf(w1, s1, acc);
}

__global__ void __launch_bounds__(BDIM, 4) wmse_fused(
    const float* __restrict__ in,
    const int*   __restrict__ tg,
    const float* __restrict__ w,
    float*       __restrict__ out)
{
    const int lane = threadIdx.x & 31;
    const int wid  = threadIdx.x >> 5;
    const int gw   = blockIdx.x * WPB + wid;

    // Preload the 7 class weights into lanes 0..6 (one reg per lane).
    float w_reg = 0.0f;
    if (lane < 7) w_reg = __ldg(&w[lane]);

    float acc = 0.0f;   // sum of w[cls_row] * diff^2 (un-normalized)
    float pen = 0.0f;   // range penalty sum

    // ---- flat, vector-parallel tail FIRST: 932 remainder groups ------------
    {
        const int tidg = blockIdx.x * BDIM + threadIdx.x;
        const float4* in4t = reinterpret_cast<const float4*>(in + TAIL_E0);
        const int4*   tg4t = reinterpret_cast<const int4*>(tg + TAIL_E0);

        for (int v = tidg; v < NTV; v += NTHR) {       // 1 or 2 iterations
            const float4 xv = __ldcs(&in4t[v]);
            const int4   tv = __ldcs(&tg4t[v]);

            const unsigned L    = (unsigned)v * 4u;    // local element index
            const unsigned rowL = L / 21u;             // compiler: magic mul
            const unsigned rem  = L - rowL * 21u;

            const float d0 = xv.x - (float)tv.x;
            const float d1 = xv.y - (float)tv.y;
            const float d2 = xv.z - (float)tv.z;
            const float d3 = xv.w - (float)tv.w;

            float s0 = 0.0f, s1 = 0.0f;
            if (rem + 0u < 21u) s0 = fmaf(d0, d0, s0); else s1 = fmaf(d0, d0, s1);
            if (rem + 1u < 21u) s0 = fmaf(d1, d1, s0); else s1 = fmaf(d1, d1, s1);
            if (rem + 2u < 21u) s0 = fmaf(d2, d2, s0); else s1 = fmaf(d2, d2, s1);
            if (rem + 3u < 21u) s0 = fmaf(d3, d3, s0); else s1 = fmaf(d3, d3, s1);

            const unsigned rowL1 = (rowL + 1u < TAIL_ROWS) ? rowL + 1u : rowL;
            const size_t gr0 = (size_t)(TAIL_ROW0 + rowL)  * NF;
            const size_t gr1 = (size_t)(TAIL_ROW0 + rowL1) * NF;
            const int cls0 = __ldg(&tg[gr0 + 2]) / 100 - 1;
            const int cls1 = __ldg(&tg[gr1 + 2]) / 100 - 1;
            acc = fmaf(__ldg(&w[cls0]), s0, acc);
            acc = fmaf(__ldg(&w[cls1]), s1, acc);

            // Penalty: each row's element-1 lies in exactly one vector.
            if (rem <= 1u) {                           // own row's position 1
                const float pv = (float)i4_at(tv, 1u - rem);
                const float u  = fmaxf(fmaxf(-pv, pv - 1000.0f), 0.0f);
                pen = fmaf(u, u, pen);
            }
            if (rem >= 19u) {                          // next row's position 1
                const float pv = (float)i4_at(tv, 22u - rem);
                const float u  = fmaxf(fmaxf(-pv, pv - 1000.0f), 0.0f);
                pen = fmaf(u, u, pen);
            }
        }
    }

    // Meta prologue for the first main iteration.
    int t1c, t2c;
    {
        const size_t mrow = (size_t)(gw * 32 + lane) * NF;
        t1c = __ldg(&tg[mrow + 1]);
        t2c = __ldg(&tg[mrow + 2]);
    }

    // ---- main loop: exactly ITERS groups per warp, no bounds checks --------
    #pragma unroll 1
    for (int it = 0; it < ITERS; it++) {
        const int g = gw + it * TOTW;
        const size_t base = (size_t)g * GELEM;

        const int cls = t2c / 100 - 1;                 // {100..700} -> {0..6}
        const float wl = __shfl_sync(0xFFFFFFFFu, w_reg, cls);

        {   // Branchless range penalty on t1.
            const float v = (float)t1c;
            const float u = fmaxf(fmaxf(-v, v - 1000.0f), 0.0f);
            pen = fmaf(u, u, pen);
        }

        const float4* in4 = reinterpret_cast<const float4*>(in + base);
        const int4*   tg4 = reinterpret_cast<const int4*>(tg + base);

        // phase A: vectors 0..2 (6 LDG.128 in flight)
        float4 xa0 = __ldcs(&in4[0 * 32 + lane]);
        float4 xa1 = __ldcs(&in4[1 * 32 + lane]);
        float4 xa2 = __ldcs(&in4[2 * 32 + lane]);
        int4   ta0 = __ldcs(&tg4[0 * 32 + lane]);
        int4   ta1 = __ldcs(&tg4[1 * 32 + lane]);
        int4   ta2 = __ldcs(&tg4[2 * 32 + lane]);

        proc_vec(xa0, ta0, (unsigned)(0 * 32 + lane) * 4u, wl, acc);
        proc_vec(xa1, ta1, (unsigned)(1 * 32 + lane) * 4u, wl, acc);
        proc_vec(xa2, ta2, (unsigned)(2 * 32 + lane) * 4u, wl, acc);

        // phase B: vectors 3,4 + 8-lane tail vector 5
        float4 xb0 = __ldcs(&in4[3 * 32 + lane]);
        float4 xb1 = __ldcs(&in4[4 * 32 + lane]);
        int4   tb0 = __ldcs(&tg4[3 * 32 + lane]);
        int4   tb1 = __ldcs(&tg4[4 * 32 + lane]);

        float4 xb2 = make_float4(0.f, 0.f, 0.f, 0.f);
        int4   tb2 = make_int4(0, 0, 0, 0);
        if (lane < NVEC - 160) {                      // lanes 0..7 carry the tail
            xb2 = __ldcs(&in4[160 + lane]);
            tb2 = __ldcs(&tg4[160 + lane]);
        }

        // prefetch NEXT iteration's meta (overlaps phase-B consume); skip on
        // the final iteration (no consumer).
        if (it < ITERS - 1) {
            const size_t mrow = (size_t)((size_t)(g + TOTW) * 32 + lane) * NF;
            t1c = __ldg(&tg[mrow + 1]);
            t2c = __ldg(&tg[mrow + 2]);
        }

        proc_vec(xb0, tb0, (unsigned)(3 * 32 + lane) * 4u, wl, acc);
        proc_vec(xb1, tb1, (unsigned)(4 * 32 + lane) * 4u, wl, acc);
        proc_vec(xb2, tb2, (unsigned)(5 * 32 + lane) * 4u, wl, acc);
    }

    // ---- warp reduce (fp32), then double across warps ----------------------
    #pragma unroll
    for (int off = 16; off > 0; off >>= 1) {
        acc += __shfl_down_sync(0xFFFFFFFFu, acc, off);
        pen += __shfl_down_sync(0xFFFFFFFFu, pen, off);
    }

    __shared__ float sa[WPB], sp[WPB];
    __shared__ bool  s_last;
    if (lane == 0) { sa[wid] = acc; sp[wid] = pen; }
    __syncthreads();

    if (threadIdx.x == 0) {
        double a = 0.0, p = 0.0;
        #pragma unroll
        for (int i = 0; i < WPB; i++) { a += (double)sa[i]; p += (double)sp[i]; }
        g_pa[blockIdx.x] = a;
        g_pp[blockIdx.x] = p;
        __threadfence();
        const unsigned old = atomicAdd(&g_ctr, 1u);
        s_last = (old == (unsigned)(NB - 1));
    }
    __syncthreads();

    // ---- last-arriving block folds all partials (L2-resident) --------------
    if (s_last) {
        double a = 0.0, p = 0.0;
        for (int i = threadIdx.x; i < NB; i += BDIM) { a += g_pa[i]; p += g_pp[i]; }

        #pragma unroll
        for (int off = 16; off > 0; off >>= 1) {
            a += __shfl_down_sync(0xFFFFFFFFu, a, off);
            p += __shfl_down_sync(0xFFFFFFFFu, p, off);
        }
        __shared__ double da[WPB], dp[WPB];
        if (lane == 0) { da[wid] = a; dp[wid] = p; }
        __syncthreads();
        if (threadIdx.x == 0) {
            double fa = 0.0, fp = 0.0;
            #pragma unroll
            for (int i = 0; i < WPB; i++) { fa += da[i]; fp += dp[i]; }
            out[0] = (float)(fa / ((double)BTOT * (double)NF) + fp);
            g_ctr = 0;   // re-arm for the next graph replay
        }
    }
}

extern "C" void kernel_launch(void* const* d_in, const int* in_sizes, int n_in,
                              void* d_out, int out_size)
{
    const float* in = (const float*)d_in[0];   // inputs  [B, 21] f32
    const int*   tg = (const int*)d_in[1];     // targets [B, 21] i32
    const float* w  = (const float*)d_in[2];   // weights [7]     f32
    float*       out = (float*)d_out;          // scalar  f32

    wmse_fused<<<NB, BDIM>>>(in, tg, w, out);
}

// round 14
// speedup vs baseline: 1.1722x; 1.1722x over previous
#include <cuda_runtime.h>
#include <cuda_bf16.h>

// Fixed shape: B=2,000,000 rows x F=21 cols, 7 classes (targets[:,2] in
// {100..700}), range penalty on targets[:,1] vs (0, 1000).
constexpr int NF    = 21;
constexpr int BTOT  = 2000000;
constexpr int GELEM = 32 * NF;            // 672 floats per 32-row group
constexpr int NVEC  = GELEM / 4;          // 168 float4 per group
constexpr int NGRP  = BTOT / 32;          // 62500 groups

constexpr int BDIM  = 256;
constexpr int WPB   = BDIM / 32;          // 8 warps/block
constexpr int NB    = 592;                // 148 SMs * 4 CTAs
constexpr int TOTW  = NB * WPB;           // 4736 warps grid-wide
constexpr int NTHR  = NB * BDIM;          // 151552 threads grid-wide

// Balanced split: every warp does exactly ITERS groups; the remainder is
// processed vector-parallel by all threads AFTER the main loop (per-warp
// staggering hides its dependent meta chains inside other warps' streaming).
constexpr int ITERS     = NGRP / TOTW;              // 13
constexpr int MAIN_GRP  = ITERS * TOTW;             // 61568 groups
constexpr int TAIL_GRP  = NGRP - MAIN_GRP;          // 932 groups
constexpr int NTV       = TAIL_GRP * NVEC;          // 156576 tail float4s
constexpr unsigned TAIL_ROWS = TAIL_GRP * 32;       // 29824
constexpr unsigned TAIL_ROW0 = MAIN_GRP * 32;       // 1970176
constexpr long long TAIL_E0  = (long long)MAIN_GRP * GELEM;

__device__ double       g_pa[NB];
__device__ double       g_pp[NB];
__device__ unsigned int g_ctr = 0;        // re-armed by the finishing block

__device__ __forceinline__ int i4_at(int4 t, unsigned j) {
    switch (j) { case 0u: return t.x; case 1u: return t.y; case 2u: return t.z; default: return t.w; }
}

// One float4/int4 pair in the main loop: 4 consecutive elements span at most
// 2 rows. Split sums at the row boundary; 2 shfls apply row weights.
__device__ __forceinline__ void proc_vec(
    float4 xv, int4 tv, unsigned e0, float wl, float& acc)
{
    const unsigned r0  = (e0 * 6243u) >> 17;           // e0/21, exact here
    const unsigned rem = e0 - r0 * 21u;                // 0..20

    const float d0 = xv.x - (float)tv.x;
    const float d1 = xv.y - (float)tv.y;
    const float d2 = xv.z - (float)tv.z;
    const float d3 = xv.w - (float)tv.w;

    float s0 = 0.0f, s1 = 0.0f;
    if (rem + 0u < 21u) s0 = fmaf(d0, d0, s0); else s1 = fmaf(d0, d0, s1);
    if (rem + 1u < 21u) s0 = fmaf(d1, d1, s0); else s1 = fmaf(d1, d1, s1);
    if (rem + 2u < 21u) s0 = fmaf(d2, d2, s0); else s1 = fmaf(d2, d2, s1);
    if (rem + 3u < 21u) s0 = fmaf(d3, d3, s0); else s1 = fmaf(d3, d3, s1);

    const float w0 = __shfl_sync(0xFFFFFFFFu, wl, (int)(r0 & 31u));
    const float w1 = __shfl_sync(0xFFFFFFFFu, wl, (int)((r0 + 1u) & 31u));
    acc = fmaf(w0, s0, acc);
    acc = fmaf(w1, s1, acc);
}

__global__ void __launch_bounds__(BDIM, 4) wmse_fused(
    const float* __restrict__ in,
    const int*   __restrict__ tg,
    const float* __restrict__ w,
    float*       __restrict__ out)
{
    const int lane = threadIdx.x & 31;
    const int wid  = threadIdx.x >> 5;
    const int gw   = blockIdx.x * WPB + wid;

    // Preload the 7 class weights into lanes 0..6 (one reg per lane).
    float w_reg = 0.0f;
    if (lane < 7) w_reg = __ldg(&w[lane]);

    float acc = 0.0f;   // sum of w[cls_row] * diff^2 (un-normalized)
    float pen = 0.0f;   // range penalty sum

    // Meta prologue for the first iteration.
    int t1c, t2c;
    {
        const size_t mrow = (size_t)(gw * 32 + lane) * NF;
        t1c = __ldg(&tg[mrow + 1]);
        t2c = __ldg(&tg[mrow + 2]);
    }

    // ---- main loop: exactly ITERS groups per warp, no bounds checks --------
    #pragma unroll 1
    for (int it = 0; it < ITERS; it++) {
        const int g = gw + it * TOTW;
        const size_t base = (size_t)g * GELEM;

        const int cls = t2c / 100 - 1;                 // {100..700} -> {0..6}
        const float wl = __shfl_sync(0xFFFFFFFFu, w_reg, cls);

        {   // Branchless range penalty on t1.
            const float v = (float)t1c;
            const float u = fmaxf(fmaxf(-v, v - 1000.0f), 0.0f);
            pen = fmaf(u, u, pen);
        }

        const float4* in4 = reinterpret_cast<const float4*>(in + base);
        const int4*   tg4 = reinterpret_cast<const int4*>(tg + base);

        // phase A: vectors 0..2 (6 LDG.128 in flight)
        float4 xa0 = __ldcs(&in4[0 * 32 + lane]);
        float4 xa1 = __ldcs(&in4[1 * 32 + lane]);
        float4 xa2 = __ldcs(&in4[2 * 32 + lane]);
        int4   ta0 = __ldcs(&tg4[0 * 32 + lane]);
        int4   ta1 = __ldcs(&tg4[1 * 32 + lane]);
        int4   ta2 = __ldcs(&tg4[2 * 32 + lane]);

        proc_vec(xa0, ta0, (unsigned)(0 * 32 + lane) * 4u, wl, acc);
        proc_vec(xa1, ta1, (unsigned)(1 * 32 + lane) * 4u, wl, acc);
        proc_vec(xa2, ta2, (unsigned)(2 * 32 + lane) * 4u, wl, acc);

        // phase B: vectors 3,4 + 8-lane tail vector 5
        float4 xb0 = __ldcs(&in4[3 * 32 + lane]);
        float4 xb1 = __ldcs(&in4[4 * 32 + lane]);
        int4   tb0 = __ldcs(&tg4[3 * 32 + lane]);
        int4   tb1 = __ldcs(&tg4[4 * 32 + lane]);

        float4 xb2 = make_float4(0.f, 0.f, 0.f, 0.f);
        int4   tb2 = make_int4(0, 0, 0, 0);
        if (lane < NVEC - 160) {                      // lanes 0..7 carry the tail
            xb2 = __ldcs(&in4[160 + lane]);
            tb2 = __ldcs(&tg4[160 + lane]);
        }

        // prefetch NEXT iteration's meta (overlaps phase-B consume)
        {
            const int gn = g + TOTW;
            const size_t mrow = (gn < NGRP)
                ? (size_t)((size_t)gn * 32 + lane) * NF
                : (size_t)lane * NF;                  // safe dummy, values unused
            t1c = __ldg(&tg[mrow + 1]);
            t2c = __ldg(&tg[mrow + 2]);
        }

        proc_vec(xb0, tb0, (unsigned)(3 * 32 + lane) * 4u, wl, acc);
        proc_vec(xb1, tb1, (unsigned)(4 * 32 + lane) * 4u, wl, acc);
        proc_vec(xb2, tb2, (unsigned)(5 * 32 + lane) * 4u, wl, acc);
    }

    // ---- flat, vector-parallel tail: remaining 932 groups ------------------
    {
        const int tidg = blockIdx.x * BDIM + threadIdx.x;
        const float4* in4t = reinterpret_cast<const float4*>(in + TAIL_E0);
        const int4*   tg4t = reinterpret_cast<const int4*>(tg + TAIL_E0);

        for (int v = tidg; v < NTV; v += NTHR) {       // 1 or 2 iterations
            const float4 xv = __ldcs(&in4t[v]);
            const int4   tv = __ldcs(&tg4t[v]);

            const unsigned L    = (unsigned)v * 4u;    // local element index
            const unsigned rowL = L / 21u;             // compiler: magic mul
            const unsigned rem  = L - rowL * 21u;

            const float d0 = xv.x - (float)tv.x;
            const float d1 = xv.y - (float)tv.y;
            const float d2 = xv.z - (float)tv.z;
            const float d3 = xv.w - (float)tv.w;

            float s0 = 0.0f, s1 = 0.0f;
            if (rem + 0u < 21u) s0 = fmaf(d0, d0, s0); else s1 = fmaf(d0, d0, s1);
            if (rem + 1u < 21u) s0 = fmaf(d1, d1, s0); else s1 = fmaf(d1, d1, s1);
            if (rem + 2u < 21u) s0 = fmaf(d2, d2, s0); else s1 = fmaf(d2, d2, s1);
            if (rem + 3u < 21u) s0 = fmaf(d3, d3, s0); else s1 = fmaf(d3, d3, s1);

            const unsigned rowL1 = (rowL + 1u < TAIL_ROWS) ? rowL + 1u : rowL;
            const size_t gr0 = (size_t)(TAIL_ROW0 + rowL)  * NF;
            const size_t gr1 = (size_t)(TAIL_ROW0 + rowL1) * NF;
            const int cls0 = __ldg(&tg[gr0 + 2]) / 100 - 1;
            const int cls1 = __ldg(&tg[gr1 + 2]) / 100 - 1;
            acc = fmaf(__ldg(&w[cls0]), s0, acc);
            acc = fmaf(__ldg(&w[cls1]), s1, acc);

            // Penalty: each row's element-1 lies in exactly one vector.
            if (rem <= 1u) {                           // own row's position 1
                const float pv = (float)i4_at(tv, 1u - rem);
                const float u  = fmaxf(fmaxf(-pv, pv - 1000.0f), 0.0f);
                pen = fmaf(u, u, pen);
            }
            if (rem >= 19u) {                          // next row's position 1
                const float pv = (float)i4_at(tv, 22u - rem);
                const float u  = fmaxf(fmaxf(-pv, pv - 1000.0f), 0.0f);
                pen = fmaf(u, u, pen);
            }
        }
    }

    // ---- warp reduce (fp32), then double across warps ----------------------
    #pragma unroll
    for (int off = 16; off > 0; off >>= 1) {
        acc += __shfl_down_sync(0xFFFFFFFFu, acc, off);
        pen += __shfl_down_sync(0xFFFFFFFFu, pen, off);
    }

    __shared__ float sa[WPB], sp[WPB];
    __shared__ bool  s_last;
    if (lane == 0) { sa[wid] = acc; sp[wid] = pen; }
    __syncthreads();

    if (threadIdx.x == 0) {
        double a = 0.0, p = 0.0;
        #pragma unroll
        for (int i = 0; i < WPB; i++) { a += (double)sa[i]; p += (double)sp[i]; }
        g_pa[blockIdx.x] = a;
        g_pp[blockIdx.x] = p;
        __threadfence();
        const unsigned old = atomicAdd(&g_ctr, 1u);
        s_last = (old == (unsigned)(NB - 1));
    }
    __syncthreads();

    // ---- last-arriving block folds all partials (L2-resident) --------------
    if (s_last) {
        double a = 0.0, p = 0.0;
        for (int i = threadIdx.x; i < NB; i += BDIM) { a += g_pa[i]; p += g_pp[i]; }

        #pragma unroll
        for (int off = 16; off > 0; off >>= 1) {
            a += __shfl_down_sync(0xFFFFFFFFu, a, off);
            p += __shfl_down_sync(0xFFFFFFFFu, p, off);
        }
        __shared__ double da[WPB], dp[WPB];
        if (lane == 0) { da[wid] = a; dp[wid] = p; }
        __syncthreads();
        if (threadIdx.x == 0) {
            double fa = 0.0, fp = 0.0;
            #pragma unroll
            for (int i = 0; i < WPB; i++) { fa += da[i]; fp += dp[i]; }
            out[0] = (float)(fa / ((double)BTOT * (double)NF) + fp);
            g_ctr = 0;   // re-arm for the next graph replay
        }
    }
}

extern "C" void kernel_launch(void* const* d_in, const int* in_sizes, int n_in,
                              void* d_out, int out_size)
{
    const float* in = (const float*)d_in[0];   // inputs  [B, 21] f32
    const int*   tg = (const int*)d_in[1];     // targets [B, 21] i32
    const float* w  = (const float*)d_in[2];   // weights [7]     f32
    float*       out = (float*)d_out;          // scalar  f32

    wmse_fused<<<NB, BDIM>>>(in, tg, w, out);
}